// round 1
// baseline (speedup 1.0000x reference)
#include <cuda_runtime.h>
#include <cstdint>

#define S   8192
#define M   1024
#define FD  4096
#define E   8
#define CAP 2560   // 2*S/E*1.25

// ---------------- scratch (static __device__; no allocations) ----------------
__device__ int   d_idx1[S], d_idx2[S];
__device__ int   d_pos1[S], d_pos2l[S];
__device__ int   d_sp1[S],  d_sp2[S];
__device__ float d_g1r[S],  d_g2r[S], d_w1f[S], d_w2f[S];
__device__ float d_probs[S * E];
__device__ int   d_slot_token[E * CAP];
__device__ int   d_used[E];
__device__ float d_h[(size_t)E * CAP * FD];   // 335 MB intermediate
__device__ float d_y[(size_t)E * CAP * M];    // 84 MB expert outputs

// ---------------- gating: logits, softmax, top-2 ----------------
__global__ void gate_kernel(const float* __restrict__ x, const float* __restrict__ wg)
{
    __shared__ float wgs[M * E];          // 32 KB
    int tid = threadIdx.x;
    for (int i = tid; i < M * E; i += blockDim.x) wgs[i] = wg[i];
    __syncthreads();

    int warp = tid >> 5, lane = tid & 31;
    int s = blockIdx.x * 8 + warp;        // 8 tokens per 256-thread block
    const float* xr = x + (size_t)s * M;

    float acc[E];
#pragma unroll
    for (int e = 0; e < E; e++) acc[e] = 0.f;
    for (int m = lane; m < M; m += 32) {
        float xv = xr[m];
        const float* w = &wgs[m * E];
#pragma unroll
        for (int e = 0; e < E; e++) acc[e] += xv * w[e];
    }
#pragma unroll
    for (int e = 0; e < E; e++) {
#pragma unroll
        for (int o = 16; o > 0; o >>= 1)
            acc[e] += __shfl_down_sync(0xffffffffu, acc[e], o);
    }
    if (lane == 0) {
        float mx = acc[0];
#pragma unroll
        for (int e = 1; e < E; e++) mx = fmaxf(mx, acc[e]);
        float p[E]; float sum = 0.f;
#pragma unroll
        for (int e = 0; e < E; e++) { p[e] = expf(acc[e] - mx); sum += p[e]; }
        float inv = 1.f / sum;
#pragma unroll
        for (int e = 0; e < E; e++) { p[e] *= inv; d_probs[s * E + e] = p[e]; }
        // first-occurrence argmax (matches jnp.argmax)
        int i1 = 0;
#pragma unroll
        for (int e = 1; e < E; e++) if (acc[e] > acc[i1]) i1 = e;
        int i2 = -1;
#pragma unroll
        for (int e = 0; e < E; e++) {
            if (e == i1) continue;
            if (i2 < 0 || acc[e] > acc[i2]) i2 = e;
        }
        d_idx1[s] = i1; d_idx2[s] = i2;
        d_g1r[s] = p[i1]; d_g2r[s] = p[i2];
    }
}

// ---------------- order-dependent prefix sums, capacity, scatter, l_aux ----------------
__global__ void scan_kernel(float* __restrict__ out, int write_laux)
{
    __shared__ unsigned char si1[S], si2[S];   // 16 KB
    __shared__ int sn1[E], sn2[E];
    __shared__ float sme[E];
    int tid = threadIdx.x;                     // 512 threads
    for (int i = tid; i < S; i += blockDim.x) {
        si1[i] = (unsigned char)d_idx1[i];
        si2[i] = (unsigned char)d_idx2[i];
    }
    __syncthreads();

    int warp = tid >> 5, lane = tid & 31;
    if (warp < E) {                            // per-expert scan of first choices
        int e = warp; int run = 0;
        for (int base = 0; base < S; base += 32) {
            bool m = (si1[base + lane] == e);
            unsigned bal = __ballot_sync(0xffffffffu, m);
            if (m) d_pos1[base + lane] = run + __popc(bal & ((1u << lane) - 1u));
            run += __popc(bal);
        }
        if (lane == 0) sn1[e] = run;
    } else {                                   // per-expert scan of second choices
        int e = warp - E; int run = 0;
        for (int base = 0; base < S; base += 32) {
            bool m = (si2[base + lane] == e);
            unsigned bal = __ballot_sync(0xffffffffu, m);
            if (m) d_pos2l[base + lane] = run + __popc(bal & ((1u << lane) - 1u));
            run += __popc(bal);
        }
        if (lane == 0) sn2[e] = run;
    }
    __syncthreads();

    for (int s = tid; s < S; s += blockDim.x) {
        int e1 = si1[s], e2 = si2[s];
        int p1 = d_pos1[s];
        int p2 = d_pos2l[s] + sn1[e2];         // second choices slot after all first choices
        bool k1 = p1 < CAP, k2 = p2 < CAP;
        float a = d_g1r[s], b = d_g2r[s];
        float inv = 1.f / fmaxf(a + b, 1e-9f); // denom from raw gates (pre-mask)
        d_w1f[s] = k1 ? a * inv : 0.f;
        d_w2f[s] = k2 ? b * inv : 0.f;
        d_sp1[s] = min(p1, CAP - 1);
        d_sp2[s] = min(p2, CAP - 1);
        if (k1) d_slot_token[e1 * CAP + p1] = s;
        if (k2) d_slot_token[e2 * CAP + p2] = s;
    }
    if (tid < E) d_used[tid] = min(sn1[tid] + sn2[tid], CAP);

    if (write_laux) {
        __syncthreads();
        if (warp < E) {                        // deterministic fixed-order reduction
            int e = warp; float part = 0.f;
            for (int s = lane; s < S; s += 32) part += d_probs[s * E + e];
#pragma unroll
            for (int o = 16; o > 0; o >>= 1)
                part += __shfl_down_sync(0xffffffffu, part, o);
            if (lane == 0) sme[e] = part;
        }
        __syncthreads();
        if (tid == 0) {
            float la = 0.f;
            for (int e = 0; e < E; e++)
                la += (sme[e] / (float)S) * ((float)sn1[e] / (float)S);
            out[(size_t)S * M] = la * (float)E;
        }
    }
}

// ---------------- GEMM1: h[e,c,f] = relu(x[tok(e,c)] @ w1[e] + b1[e]) ----------------
__global__ __launch_bounds__(256) void gemm1_kernel(const float* __restrict__ x,
                                                    const float* __restrict__ w1,
                                                    const float* __restrict__ b1)
{
    int e = blockIdx.z;
    int used = d_used[e];
    int m0 = blockIdx.y * 128;
    if (m0 >= used) return;
    int n0 = blockIdx.x * 128;

    __shared__ float As[16][128];
    __shared__ float Bs[16][128];
    __shared__ int toks[128];
    int tid = threadIdx.x;
    for (int r = tid; r < 128; r += 256) {
        int row = m0 + r;
        toks[r] = (row < used) ? d_slot_token[e * CAP + row] : -1;
    }
    const float* B = w1 + (size_t)e * M * FD;

    float acc[8][8];
#pragma unroll
    for (int i = 0; i < 8; i++)
#pragma unroll
        for (int j = 0; j < 8; j++) acc[i][j] = 0.f;

    int ar = tid >> 2, ac = (tid & 3) << 2;
    int br = tid >> 5, bc = (tid & 31) << 2;
    int tx = tid & 15, ty = tid >> 4;
    __syncthreads();

    for (int k0 = 0; k0 < M; k0 += 16) {
#pragma unroll
        for (int h2 = 0; h2 < 2; h2++) {
            int r = ar + h2 * 64;
            int t = toks[r];
            float4 v = make_float4(0.f, 0.f, 0.f, 0.f);
            if (t >= 0) v = *(const float4*)(x + (size_t)t * M + k0 + ac);
            As[ac + 0][r] = v.x; As[ac + 1][r] = v.y;
            As[ac + 2][r] = v.z; As[ac + 3][r] = v.w;
        }
#pragma unroll
        for (int h2 = 0; h2 < 2; h2++) {
            int rk = br + h2 * 8;
            *(float4*)&Bs[rk][bc] = *(const float4*)(B + (size_t)(k0 + rk) * FD + n0 + bc);
        }
        __syncthreads();
#pragma unroll
        for (int kk = 0; kk < 16; kk++) {
            float ra[8], rb[8];
#pragma unroll
            for (int i = 0; i < 8; i++) ra[i] = As[kk][ty + i * 16];
#pragma unroll
            for (int j = 0; j < 8; j++) rb[j] = Bs[kk][tx + j * 16];
#pragma unroll
            for (int i = 0; i < 8; i++)
#pragma unroll
                for (int j = 0; j < 8; j++)
                    acc[i][j] += ra[i] * rb[j];
        }
        __syncthreads();
    }

    const float* bias = b1 + (size_t)e * FD;
    float* H = d_h + (size_t)e * CAP * FD;
#pragma unroll
    for (int i = 0; i < 8; i++) {
        int row = m0 + ty + i * 16;
        if (row < used) {
#pragma unroll
            for (int j = 0; j < 8; j++) {
                int col = n0 + tx + j * 16;
                H[(size_t)row * FD + col] = fmaxf(acc[i][j] + bias[col], 0.f);
            }
        }
    }
}

// ---------------- GEMM2: y[e,c,m] = h[e,c] @ w2[e] + b2[e] ----------------
__global__ __launch_bounds__(256) void gemm2_kernel(const float* __restrict__ w2,
                                                    const float* __restrict__ b2)
{
    int e = blockIdx.z;
    int used = d_used[e];
    int m0 = blockIdx.y * 128;
    if (m0 >= used) return;
    int n0 = blockIdx.x * 128;

    __shared__ float As[16][128];
    __shared__ float Bs[16][128];
    int tid = threadIdx.x;
    const float* A = d_h + (size_t)e * CAP * FD;
    const float* B = w2 + (size_t)e * FD * M;

    float acc[8][8];
#pragma unroll
    for (int i = 0; i < 8; i++)
#pragma unroll
        for (int j = 0; j < 8; j++) acc[i][j] = 0.f;

    int ar = tid >> 2, ac = (tid & 3) << 2;
    int br = tid >> 5, bc = (tid & 31) << 2;
    int tx = tid & 15, ty = tid >> 4;

    for (int k0 = 0; k0 < FD; k0 += 16) {
#pragma unroll
        for (int h2 = 0; h2 < 2; h2++) {
            int r = ar + h2 * 64;
            float4 v = *(const float4*)(A + (size_t)(m0 + r) * FD + k0 + ac);
            As[ac + 0][r] = v.x; As[ac + 1][r] = v.y;
            As[ac + 2][r] = v.z; As[ac + 3][r] = v.w;
        }
#pragma unroll
        for (int h2 = 0; h2 < 2; h2++) {
            int rk = br + h2 * 8;
            *(float4*)&Bs[rk][bc] = *(const float4*)(B + (size_t)(k0 + rk) * M + n0 + bc);
        }
        __syncthreads();
#pragma unroll
        for (int kk = 0; kk < 16; kk++) {
            float ra[8], rb[8];
#pragma unroll
            for (int i = 0; i < 8; i++) ra[i] = As[kk][ty + i * 16];
#pragma unroll
            for (int j = 0; j < 8; j++) rb[j] = Bs[kk][tx + j * 16];
#pragma unroll
            for (int i = 0; i < 8; i++)
#pragma unroll
                for (int j = 0; j < 8; j++)
                    acc[i][j] += ra[i] * rb[j];
        }
        __syncthreads();
    }

    const float* bias = b2 + (size_t)e * M;
    float* Y = d_y + (size_t)e * CAP * M;
#pragma unroll
    for (int i = 0; i < 8; i++) {
        int row = m0 + ty + i * 16;
        if (row < used) {
#pragma unroll
            for (int j = 0; j < 8; j++) {
                int col = n0 + tx + j * 16;
                Y[(size_t)row * M + col] = acc[i][j] + bias[col];
            }
        }
    }
}

// ---------------- combine: out[s] = g1*y(e1,p1) + g2*y(e2,p2) ----------------
__global__ void combine_kernel(float* __restrict__ out)
{
    int s = blockIdx.x;
    int t = threadIdx.x;                       // 256 threads, 4 floats each
    float a = d_w1f[s], b = d_w2f[s];
    float4 r = make_float4(0.f, 0.f, 0.f, 0.f);
    if (a != 0.f) {
        const float4* y = (const float4*)(d_y + ((size_t)d_idx1[s] * CAP + d_sp1[s]) * M);
        float4 v = y[t];
        r.x += a * v.x; r.y += a * v.y; r.z += a * v.z; r.w += a * v.w;
    }
    if (b != 0.f) {
        const float4* y = (const float4*)(d_y + ((size_t)d_idx2[s] * CAP + d_sp2[s]) * M);
        float4 v = y[t];
        r.x += b * v.x; r.y += b * v.y; r.z += b * v.z; r.w += b * v.w;
    }
    ((float4*)(out + (size_t)s * M))[t] = r;
}

// ---------------- launch ----------------
extern "C" void kernel_launch(void* const* d_in, const int* in_sizes, int n_in,
                              void* d_out, int out_size)
{
    const float* x  = (const float*)d_in[0];
    const float* wg = (const float*)d_in[1];
    const float* w1 = (const float*)d_in[2];
    const float* b1 = (const float*)d_in[3];
    const float* w2 = (const float*)d_in[4];
    const float* b2 = (const float*)d_in[5];
    float* out = (float*)d_out;
    int write_laux = (out_size > S * M) ? 1 : 0;

    gate_kernel<<<S / 8, 256>>>(x, wg);
    scan_kernel<<<1, 512>>>(out, write_laux);
    gemm1_kernel<<<dim3(FD / 128, CAP / 128, E), 256>>>(x, w1, b1);
    gemm2_kernel<<<dim3(M / 128, CAP / 128, E), 256>>>(w2, b2);
    combine_kernel<<<S, 256>>>(out);
}

// round 2
// speedup vs baseline: 2.8149x; 2.8149x over previous
#include <cuda_runtime.h>
#include <cstdint>

#define S   8192
#define M   1024
#define FD  4096
#define E   8
#define CAP 2560   // 2*S/E*1.25

// ---------------- scratch (static __device__; no allocations) ----------------
__device__ int   d_idx1[S], d_idx2[S];
__device__ int   d_pos1[S], d_pos2l[S];
__device__ int   d_sp1[S],  d_sp2[S];
__device__ float d_g1r[S],  d_g2r[S], d_w1f[S], d_w2f[S];
__device__ float d_probs[S * E];
__device__ int   d_slot_token[E * CAP];
__device__ int   d_used[E];
__device__ float d_h[(size_t)E * CAP * FD];   // 335 MB intermediate
__device__ float d_y[(size_t)E * CAP * M];    // 84 MB expert outputs

// round-to-nearest f32 -> tf32 (kept in b32)
__device__ __forceinline__ uint32_t f2tf32(float f) {
    uint32_t u;
    asm("cvt.rna.tf32.f32 %0, %1;" : "=r"(u) : "f"(f));
    return u;
}

__device__ __forceinline__ void mma_tf32(float c[4],
                                         uint32_t a0, uint32_t a1, uint32_t a2, uint32_t a3,
                                         uint32_t b0, uint32_t b1) {
    asm volatile(
        "mma.sync.aligned.m16n8k8.row.col.f32.tf32.tf32.f32 "
        "{%0,%1,%2,%3}, {%4,%5,%6,%7}, {%8,%9}, {%0,%1,%2,%3};\n"
        : "+f"(c[0]), "+f"(c[1]), "+f"(c[2]), "+f"(c[3])
        : "r"(a0), "r"(a1), "r"(a2), "r"(a3), "r"(b0), "r"(b1));
}

// ---------------- gating: logits, softmax, top-2 ----------------
__global__ void gate_kernel(const float* __restrict__ x, const float* __restrict__ wg)
{
    __shared__ float wgs[M * E];
    int tid = threadIdx.x;
    for (int i = tid; i < M * E; i += blockDim.x) wgs[i] = wg[i];
    __syncthreads();

    int warp = tid >> 5, lane = tid & 31;
    int s = blockIdx.x * 8 + warp;
    const float* xr = x + (size_t)s * M;

    float acc[E];
#pragma unroll
    for (int e = 0; e < E; e++) acc[e] = 0.f;
    for (int m = lane; m < M; m += 32) {
        float xv = xr[m];
        const float* w = &wgs[m * E];
#pragma unroll
        for (int e = 0; e < E; e++) acc[e] += xv * w[e];
    }
#pragma unroll
    for (int e = 0; e < E; e++) {
#pragma unroll
        for (int o = 16; o > 0; o >>= 1)
            acc[e] += __shfl_down_sync(0xffffffffu, acc[e], o);
    }
    if (lane == 0) {
        float mx = acc[0];
#pragma unroll
        for (int e = 1; e < E; e++) mx = fmaxf(mx, acc[e]);
        float p[E]; float sum = 0.f;
#pragma unroll
        for (int e = 0; e < E; e++) { p[e] = expf(acc[e] - mx); sum += p[e]; }
        float inv = 1.f / sum;
#pragma unroll
        for (int e = 0; e < E; e++) { p[e] *= inv; d_probs[s * E + e] = p[e]; }
        int i1 = 0;
#pragma unroll
        for (int e = 1; e < E; e++) if (acc[e] > acc[i1]) i1 = e;
        int i2 = -1;
#pragma unroll
        for (int e = 0; e < E; e++) {
            if (e == i1) continue;
            if (i2 < 0 || acc[e] > acc[i2]) i2 = e;
        }
        d_idx1[s] = i1; d_idx2[s] = i2;
        d_g1r[s] = p[i1]; d_g2r[s] = p[i2];
    }
}

// ---------------- order-dependent prefix sums, capacity, scatter, l_aux ----------------
__global__ void scan_kernel(float* __restrict__ out, int write_laux)
{
    __shared__ unsigned char si1[S], si2[S];
    __shared__ int sn1[E], sn2[E];
    __shared__ float sme[E];
    int tid = threadIdx.x;                     // 512 threads
    for (int i = tid; i < S; i += blockDim.x) {
        si1[i] = (unsigned char)d_idx1[i];
        si2[i] = (unsigned char)d_idx2[i];
    }
    __syncthreads();

    int warp = tid >> 5, lane = tid & 31;
    if (warp < E) {
        int e = warp; int run = 0;
        for (int base = 0; base < S; base += 32) {
            bool m = (si1[base + lane] == e);
            unsigned bal = __ballot_sync(0xffffffffu, m);
            if (m) d_pos1[base + lane] = run + __popc(bal & ((1u << lane) - 1u));
            run += __popc(bal);
        }
        if (lane == 0) sn1[e] = run;
    } else {
        int e = warp - E; int run = 0;
        for (int base = 0; base < S; base += 32) {
            bool m = (si2[base + lane] == e);
            unsigned bal = __ballot_sync(0xffffffffu, m);
            if (m) d_pos2l[base + lane] = run + __popc(bal & ((1u << lane) - 1u));
            run += __popc(bal);
        }
        if (lane == 0) sn2[e] = run;
    }
    __syncthreads();

    for (int s = tid; s < S; s += blockDim.x) {
        int e1 = si1[s], e2 = si2[s];
        int p1 = d_pos1[s];
        int p2 = d_pos2l[s] + sn1[e2];
        bool k1 = p1 < CAP, k2 = p2 < CAP;
        float a = d_g1r[s], b = d_g2r[s];
        float inv = 1.f / fmaxf(a + b, 1e-9f);
        d_w1f[s] = k1 ? a * inv : 0.f;
        d_w2f[s] = k2 ? b * inv : 0.f;
        d_sp1[s] = min(p1, CAP - 1);
        d_sp2[s] = min(p2, CAP - 1);
        if (k1) d_slot_token[e1 * CAP + p1] = s;
        if (k2) d_slot_token[e2 * CAP + p2] = s;
    }
    if (tid < E) d_used[tid] = min(sn1[tid] + sn2[tid], CAP);

    if (write_laux) {
        __syncthreads();
        if (warp < E) {
            int e = warp; float part = 0.f;
            for (int s = lane; s < S; s += 32) part += d_probs[s * E + e];
#pragma unroll
            for (int o = 16; o > 0; o >>= 1)
                part += __shfl_down_sync(0xffffffffu, part, o);
            if (lane == 0) sme[e] = part;
        }
        __syncthreads();
        if (tid == 0) {
            float la = 0.f;
            for (int e = 0; e < E; e++)
                la += (sme[e] / (float)S) * ((float)sn1[e] / (float)S);
            out[(size_t)S * M] = la * (float)E;
        }
    }
}

// ============================================================================
// TF32 tensor-core GEMM tile: BM=128, BN=128, BK=16, 256 threads (8 warps 2x4),
// warp tile 64x32 -> 4x4 m16n8k8 MMA tiles. A smem m-major [128][20] (pad ->
// conflict-free frag loads); B smem k-major [16][136].
// ============================================================================
#define APAD 20
#define BPAD 136

// ---------------- GEMM1: h[e,c,f] = relu(gather(x) @ w1[e] + b1[e]) ----------
__global__ __launch_bounds__(256) void gemm1_kernel(const float* __restrict__ x,
                                                    const float* __restrict__ w1,
                                                    const float* __restrict__ b1)
{
    int e = blockIdx.z;
    int used = d_used[e];
    int m0 = blockIdx.y * 128;
    if (m0 >= used) return;
    int n0 = blockIdx.x * 128;

    __shared__ uint32_t As[128 * APAD];
    __shared__ uint32_t Bs[16 * BPAD];
    __shared__ int toks[128];

    int tid = threadIdx.x;
    int lane = tid & 31, wid = tid >> 5;
    int warp_m = wid & 1, warp_n = wid >> 1;
    int wm = warp_m * 64, wn = warp_n * 32;
    int qr = lane >> 2, qc = lane & 3;

    for (int r = tid; r < 128; r += 256) {
        int row = m0 + r;
        toks[r] = (row < used) ? d_slot_token[e * CAP + row] : -1;
    }
    const float* B = w1 + (size_t)e * M * FD;

    float acc[4][4][4];
#pragma unroll
    for (int i = 0; i < 4; i++)
#pragma unroll
        for (int j = 0; j < 4; j++)
#pragma unroll
            for (int k = 0; k < 4; k++) acc[i][j][k] = 0.f;

    int ar = tid >> 2, ac = (tid & 3) << 2;   // A: 64 rows x 4-float cols per pass
    int br = tid >> 5, bc = (tid & 31) << 2;  // B: one k-row per warp
    __syncthreads();

    for (int k0 = 0; k0 < M; k0 += 16) {
#pragma unroll
        for (int h2 = 0; h2 < 2; h2++) {
            int r = ar + h2 * 64;
            int t = toks[r];
            float4 v = make_float4(0.f, 0.f, 0.f, 0.f);
            if (t >= 0) v = *(const float4*)(x + (size_t)t * M + k0 + ac);
            uint32_t* p = &As[r * APAD + ac];
            p[0] = f2tf32(v.x); p[1] = f2tf32(v.y);
            p[2] = f2tf32(v.z); p[3] = f2tf32(v.w);
        }
#pragma unroll
        for (int h2 = 0; h2 < 2; h2++) {
            int rk = br + h2 * 8;
            float4 v = *(const float4*)(B + (size_t)(k0 + rk) * FD + n0 + bc);
            uint32_t* p = &Bs[rk * BPAD + bc];
            p[0] = f2tf32(v.x); p[1] = f2tf32(v.y);
            p[2] = f2tf32(v.z); p[3] = f2tf32(v.w);
        }
        __syncthreads();

#pragma unroll
        for (int ks = 0; ks < 16; ks += 8) {
            uint32_t afr[4][4], bfr[4][2];
#pragma unroll
            for (int mt = 0; mt < 4; mt++) {
                int row = (wm + mt * 16 + qr) * APAD + ks + qc;
                afr[mt][0] = As[row];
                afr[mt][1] = As[row + 8 * APAD];
                afr[mt][2] = As[row + 4];
                afr[mt][3] = As[row + 8 * APAD + 4];
            }
#pragma unroll
            for (int nt = 0; nt < 4; nt++) {
                int col = wn + nt * 8 + qr;
                bfr[nt][0] = Bs[(ks + qc) * BPAD + col];
                bfr[nt][1] = Bs[(ks + qc + 4) * BPAD + col];
            }
#pragma unroll
            for (int mt = 0; mt < 4; mt++)
#pragma unroll
                for (int nt = 0; nt < 4; nt++)
                    mma_tf32(acc[mt][nt], afr[mt][0], afr[mt][1], afr[mt][2], afr[mt][3],
                             bfr[nt][0], bfr[nt][1]);
        }
        __syncthreads();
    }

    const float* bias = b1 + (size_t)e * FD;
    float* H = d_h + (size_t)e * CAP * FD;
#pragma unroll
    for (int mt = 0; mt < 4; mt++) {
#pragma unroll
        for (int half = 0; half < 2; half++) {
            int row = m0 + wm + mt * 16 + qr + half * 8;
            if (row < used) {
#pragma unroll
                for (int nt = 0; nt < 4; nt++) {
                    int col = n0 + wn + nt * 8 + qc * 2;
                    float bv0 = bias[col], bv1 = bias[col + 1];
                    H[(size_t)row * FD + col]     = fmaxf(acc[mt][nt][half * 2 + 0] + bv0, 0.f);
                    H[(size_t)row * FD + col + 1] = fmaxf(acc[mt][nt][half * 2 + 1] + bv1, 0.f);
                }
            }
        }
    }
}

// ---------------- GEMM2: y[e,c,m] = h[e,c] @ w2[e] + b2[e] ----------------
__global__ __launch_bounds__(256) void gemm2_kernel(const float* __restrict__ w2,
                                                    const float* __restrict__ b2)
{
    int e = blockIdx.z;
    int used = d_used[e];
    int m0 = blockIdx.y * 128;
    if (m0 >= used) return;
    int n0 = blockIdx.x * 128;

    __shared__ uint32_t As[128 * APAD];
    __shared__ uint32_t Bs[16 * BPAD];

    int tid = threadIdx.x;
    int lane = tid & 31, wid = tid >> 5;
    int warp_m = wid & 1, warp_n = wid >> 1;
    int wm = warp_m * 64, wn = warp_n * 32;
    int qr = lane >> 2, qc = lane & 3;

    const float* A = d_h + (size_t)e * CAP * FD;
    const float* B = w2 + (size_t)e * FD * M;

    float acc[4][4][4];
#pragma unroll
    for (int i = 0; i < 4; i++)
#pragma unroll
        for (int j = 0; j < 4; j++)
#pragma unroll
            for (int k = 0; k < 4; k++) acc[i][j][k] = 0.f;

    int ar = tid >> 2, ac = (tid & 3) << 2;
    int br = tid >> 5, bc = (tid & 31) << 2;

    for (int k0 = 0; k0 < FD; k0 += 16) {
#pragma unroll
        for (int h2 = 0; h2 < 2; h2++) {
            int r = ar + h2 * 64;
            float4 v = *(const float4*)(A + (size_t)(m0 + r) * FD + k0 + ac);
            uint32_t* p = &As[r * APAD + ac];
            p[0] = f2tf32(v.x); p[1] = f2tf32(v.y);
            p[2] = f2tf32(v.z); p[3] = f2tf32(v.w);
        }
#pragma unroll
        for (int h2 = 0; h2 < 2; h2++) {
            int rk = br + h2 * 8;
            float4 v = *(const float4*)(B + (size_t)(k0 + rk) * M + n0 + bc);
            uint32_t* p = &Bs[rk * BPAD + bc];
            p[0] = f2tf32(v.x); p[1] = f2tf32(v.y);
            p[2] = f2tf32(v.z); p[3] = f2tf32(v.w);
        }
        __syncthreads();

#pragma unroll
        for (int ks = 0; ks < 16; ks += 8) {
            uint32_t afr[4][4], bfr[4][2];
#pragma unroll
            for (int mt = 0; mt < 4; mt++) {
                int row = (wm + mt * 16 + qr) * APAD + ks + qc;
                afr[mt][0] = As[row];
                afr[mt][1] = As[row + 8 * APAD];
                afr[mt][2] = As[row + 4];
                afr[mt][3] = As[row + 8 * APAD + 4];
            }
#pragma unroll
            for (int nt = 0; nt < 4; nt++) {
                int col = wn + nt * 8 + qr;
                bfr[nt][0] = Bs[(ks + qc) * BPAD + col];
                bfr[nt][1] = Bs[(ks + qc + 4) * BPAD + col];
            }
#pragma unroll
            for (int mt = 0; mt < 4; mt++)
#pragma unroll
                for (int nt = 0; nt < 4; nt++)
                    mma_tf32(acc[mt][nt], afr[mt][0], afr[mt][1], afr[mt][2], afr[mt][3],
                             bfr[nt][0], bfr[nt][1]);
        }
        __syncthreads();
    }

    const float* bias = b2 + (size_t)e * M;
    float* Y = d_y + (size_t)e * CAP * M;
#pragma unroll
    for (int mt = 0; mt < 4; mt++) {
#pragma unroll
        for (int half = 0; half < 2; half++) {
            int row = m0 + wm + mt * 16 + qr + half * 8;
            if (row < used) {
#pragma unroll
                for (int nt = 0; nt < 4; nt++) {
                    int col = n0 + wn + nt * 8 + qc * 2;
                    float bv0 = bias[col], bv1 = bias[col + 1];
                    Y[(size_t)row * M + col]     = acc[mt][nt][half * 2 + 0] + bv0;
                    Y[(size_t)row * M + col + 1] = acc[mt][nt][half * 2 + 1] + bv1;
                }
            }
        }
    }
}

// ---------------- combine: out[s] = g1*y(e1,p1) + g2*y(e2,p2) ----------------
__global__ void combine_kernel(float* __restrict__ out)
{
    int s = blockIdx.x;
    int t = threadIdx.x;
    float a = d_w1f[s], b = d_w2f[s];
    float4 r = make_float4(0.f, 0.f, 0.f, 0.f);
    if (a != 0.f) {
        const float4* y = (const float4*)(d_y + ((size_t)d_idx1[s] * CAP + d_sp1[s]) * M);
        float4 v = y[t];
        r.x += a * v.x; r.y += a * v.y; r.z += a * v.z; r.w += a * v.w;
    }
    if (b != 0.f) {
        const float4* y = (const float4*)(d_y + ((size_t)d_idx2[s] * CAP + d_sp2[s]) * M);
        float4 v = y[t];
        r.x += b * v.x; r.y += b * v.y; r.z += b * v.z; r.w += b * v.w;
    }
    ((float4*)(out + (size_t)s * M))[t] = r;
}

// ---------------- launch ----------------
extern "C" void kernel_launch(void* const* d_in, const int* in_sizes, int n_in,
                              void* d_out, int out_size)
{
    const float* x  = (const float*)d_in[0];
    const float* wg = (const float*)d_in[1];
    const float* w1 = (const float*)d_in[2];
    const float* b1 = (const float*)d_in[3];
    const float* w2 = (const float*)d_in[4];
    const float* b2 = (const float*)d_in[5];
    float* out = (float*)d_out;
    int write_laux = (out_size > S * M) ? 1 : 0;

    gate_kernel<<<S / 8, 256>>>(x, wg);
    scan_kernel<<<1, 512>>>(out, write_laux);
    gemm1_kernel<<<dim3(FD / 128, CAP / 128, E), 256>>>(x, w1, b1);
    gemm2_kernel<<<dim3(M / 128, CAP / 128, E), 256>>>(w2, b2);
    combine_kernel<<<S, 256>>>(out);
}